// round 7
// baseline (speedup 1.0000x reference)
#include <cuda_runtime.h>
#include <stdint.h>

#define CC   128
#define CI   32
#define HH   128
#define WW   256
#define BB   8
#define HW   (HH*WW)

#define TW   32
#define TH   8
#define HTW  (TW + 2)   // 34
#define HTH  (TH + 2)   // 10
#define NHALO (HTH * HTW)  // 340

// Precomputed parameters (filled by prep kernel each launch; deterministic).
__device__ uint32_t g_w1m[CI][4];
__device__ float    g_inv1[CI], g_bb1[CI];
__device__ uint32_t g_w2m[CI][9];
__device__ float    g_inv2[CI], g_bb2[CI];
__device__ uint32_t g_w3m[CC];
__device__ float    g_inv3[CC], g_bb3[CC];

// ---------------------------------------------------------------------------
// Prep: ONE mask word per warp (544 words over 68 blocks x 8 warps) ->
// exactly one load+ballot per warp, all DRAM latency overlapped.
// bit c = (w > 0);  bn(z) = z*inv + bb, inv = g/sqrt(v+eps) > 0, bb = b - m*inv
// ---------------------------------------------------------------------------
__global__ void __launch_bounds__(256) prep_kernel(
    const float* __restrict__ w1, const float* __restrict__ g1,
    const float* __restrict__ b1, const float* __restrict__ m1, const float* __restrict__ v1,
    const float* __restrict__ w2, const float* __restrict__ g2,
    const float* __restrict__ b2, const float* __restrict__ m2, const float* __restrict__ v2,
    const float* __restrict__ w3, const float* __restrict__ g3,
    const float* __restrict__ b3, const float* __restrict__ m3, const float* __restrict__ v3)
{
    int tid  = threadIdx.x;
    int lane = tid & 31;
    int gw   = blockIdx.x * 8 + (tid >> 5);   // global word id 0..543

    if (gw < 128) {
        // w1: [CI][CC] word (oc, j)
        int oc = gw >> 2, j = gw & 3;
        uint32_t m = __ballot_sync(0xffffffffu, w1[oc * CC + j * 32 + lane] > 0.f);
        if (lane == 0) g_w1m[oc][j] = m;
    } else if (gw < 416) {
        // w2: [CI][CI][3][3] word (oc, t9), lane = input channel
        int idx = gw - 128;
        int oc = idx / 9, t9 = idx - oc * 9;
        uint32_t m = __ballot_sync(0xffffffffu, w2[oc * (CI * 9) + lane * 9 + t9] > 0.f);
        if (lane == 0) g_w2m[oc][t9] = m;
    } else if (gw < 544) {
        // w3: [CC][CI] word
        int c = gw - 416;
        uint32_t m = __ballot_sync(0xffffffffu, w3[c * CI + lane] > 0.f);
        if (lane == 0) g_w3m[c] = m;
    }

    if (blockIdx.x == 0) {
        if (tid < CI) {
            float inv = __fdiv_rn(g1[tid], __fsqrt_rn(__fadd_rn(v1[tid], 1e-5f)));
            g_inv1[tid] = inv;
            g_bb1[tid]  = __fadd_rn(b1[tid], -__fmul_rn(m1[tid], inv));
        } else if (tid >= 64 && tid < 64 + CI) {
            int t = tid - 64;
            float inv = __fdiv_rn(g2[t], __fsqrt_rn(__fadd_rn(v2[t], 1e-5f)));
            g_inv2[t] = inv;
            g_bb2[t]  = __fadd_rn(b2[t], -__fmul_rn(m2[t], inv));
        } else if (tid >= 128) {
            int t = tid - 128;
            float inv = __fdiv_rn(g3[t], __fsqrt_rn(__fadd_rn(v3[t], 1e-5f)));
            g_inv3[t] = inv;
            g_bb3[t]  = __fadd_rn(b3[t], -__fmul_rn(m3[t], inv));
        }
    }
}

// ---------------------------------------------------------------------------
// Fused kernel, register-disciplined (R5 retry):
//  phase 1: conv1+bn+sign over tile+halo -> sh1 bitmasks (x read once/block,
//           halo recomputed; <=32 live loads via controlled unrolling)
//  phase 2: conv2 (3x3, zero-pad AFTER binarize -> per-tap validity at border)
//  phase 3: conv3 + bn + prelu + residual (x re-read = L2 hit) + prelu, __stwt.
// 256 threads, 1 pixel/thread in phases 2-3.
// ---------------------------------------------------------------------------
__global__ void __launch_bounds__(256, 3) k_fused(
    const float* __restrict__ x, float* __restrict__ out,
    const float* __restrict__ a3p, const float* __restrict__ aoutp)
{
    __shared__ uint32_t sh1[HTH][HTW];
    __shared__ uint32_t sw1[CI][4];
    __shared__ float sinv1[CI], sbb1[CI];
    __shared__ uint32_t sw2[CI][9];
    __shared__ float sinv2[CI], sbb2[CI];
    __shared__ uint32_t sw3[CC];
    __shared__ float sinv3[CC], sbb3[CC];

    int tid = threadIdx.x;
    int tx  = tid & (TW - 1);
    int ty  = tid / TW;            // 0..7
    int w0  = blockIdx.x * TW;
    int h0  = blockIdx.y * TH;
    int b   = blockIdx.z;

    if (tid < CC) { sw3[tid] = g_w3m[tid]; sinv3[tid] = g_inv3[tid]; sbb3[tid] = g_bb3[tid]; }
    if (tid < CI) {
        sinv1[tid] = g_inv1[tid]; sbb1[tid] = g_bb1[tid];
        sinv2[tid] = g_inv2[tid]; sbb2[tid] = g_bb2[tid];
        #pragma unroll
        for (int j = 0; j < 4; j++) sw1[tid][j] = g_w1m[tid][j];
        #pragma unroll
        for (int t9 = 0; t9 < 9; t9++) sw2[tid][t9] = g_w2m[tid][t9];
    }
    __syncthreads();

    const float* xb = x + (size_t)b * (CC * HW);

    // ---- Phase 1: conv1+bn+sign over the 10x34 halo region ----
    #pragma unroll 1
    for (int it = tid; it < NHALO; it += 256) {
        int hy = it / HTW, hx = it - hy * HTW;
        int gh = h0 + hy - 1, gw = w0 + hx - 1;
        uint32_t outm = 0;
        if (gh >= 0 && gh < HH && gw >= 0 && gw < WW) {
            const float* xp = xb + (size_t)gh * WW + gw;
            uint32_t s0 = 0, s1 = 0, s2 = 0, s3 = 0;
            // <=32 outstanding loads (4 per unrolled i-iter x 8)
            #pragma unroll 8
            for (int i = 0; i < 32; i++) {
                float a = xp[(i      ) * HW];
                float c = xp[(i +  32) * HW];
                float d = xp[(i +  64) * HW];
                float e = xp[(i +  96) * HW];
                if (a > 0.f) s0 |= (1u << i);
                if (c > 0.f) s1 |= (1u << i);
                if (d > 0.f) s2 |= (1u << i);
                if (e > 0.f) s3 |= (1u << i);
            }
            #pragma unroll
            for (int oc = 0; oc < CI; oc++) {
                int pc = __popc(s0 ^ sw1[oc][0]) + __popc(s1 ^ sw1[oc][1])
                       + __popc(s2 ^ sw1[oc][2]) + __popc(s3 ^ sw1[oc][3]);
                float v = __fadd_rn(__fmul_rn((float)(128 - 2 * pc), sinv1[oc]), sbb1[oc]);
                if (v > 0.f) outm |= (1u << oc);
            }
        }
        sh1[hy][hx] = outm;
    }
    __syncthreads();

    // ---- Phase 2: conv2+bn+sign, 1 pixel/thread ----
    // Center of (ty,tx) at sh1[ty+1][tx+1]; tap t offset (t/3-1, t%3-1)
    // -> gather sh1[ty + t/3][tx + t%3].
    const bool border = (w0 == 0) | (h0 == 0) | (w0 + TW == WW) | (h0 + TH == HH);
    int gh = h0 + ty, gw = w0 + tx;

    uint32_t n[9];
    #pragma unroll
    for (int t = 0; t < 9; t++)
        n[t] = sh1[ty + t / 3][tx + t % 3];

    uint32_t h2b = 0;
    if (!border) {
        #pragma unroll
        for (int oc = 0; oc < CI; oc++) {
            int pc = 0;
            #pragma unroll
            for (int t = 0; t < 9; t++) pc += __popc(n[t] ^ sw2[oc][t]);
            float v = __fadd_rn(__fmul_rn((float)(288 - 2 * pc), sinv2[oc]), sbb2[oc]);
            if (v > 0.f) h2b |= (1u << oc);
        }
    } else {
        bool ok[9];
        #pragma unroll
        for (int t = 0; t < 9; t++) {
            int yy = gh + t / 3 - 1, xx = gw + t % 3 - 1;
            ok[t] = (yy >= 0) & (yy < HH) & (xx >= 0) & (xx < WW);
        }
        #pragma unroll
        for (int oc = 0; oc < CI; oc++) {
            int z = 0;
            #pragma unroll
            for (int t = 0; t < 9; t++) {
                int c9 = 32 - 2 * __popc(n[t] ^ sw2[oc][t]);
                z += ok[t] ? c9 : 0;
            }
            float v = __fadd_rn(__fmul_rn((float)z, sinv2[oc]), sbb2[oc]);
            if (v > 0.f) h2b |= (1u << oc);
        }
    }

    // ---- Phase 3: conv3 + bn + prelu + residual + prelu ----
    float a3   = a3p[0];
    float aout = aoutp[0];
    size_t base = (size_t)b * (CC * HW) + (size_t)gh * WW + gw;
    const float* xp = x + base;
    float* op = out + base;

    #pragma unroll 16
    for (int c = 0; c < CC; c++) {
        int z = 32 - 2 * __popc(h2b ^ sw3[c]);
        float v = __fadd_rn(__fmul_rn((float)z, sinv3[c]), sbb3[c]);
        v = (v >= 0.f) ? v : a3 * v;
        float s = v + xp[(size_t)c * HW];
        s = (s >= 0.f) ? s : aout * s;
        __stwt(op + (size_t)c * HW, s);
    }
}

// ---------------------------------------------------------------------------
extern "C" void kernel_launch(void* const* d_in, const int* in_sizes, int n_in,
                              void* d_out, int out_size)
{
    const float* x  = (const float*)d_in[0];
    const float* w1 = (const float*)d_in[1];
    const float* g1 = (const float*)d_in[2];
    const float* b1 = (const float*)d_in[3];
    const float* m1 = (const float*)d_in[4];
    const float* v1 = (const float*)d_in[5];
    // d_in[6] = a1 (unused: prelu with a>0 never changes the following sign)
    const float* w2 = (const float*)d_in[7];
    const float* g2 = (const float*)d_in[8];
    const float* b2 = (const float*)d_in[9];
    const float* m2 = (const float*)d_in[10];
    const float* v2 = (const float*)d_in[11];
    // d_in[12] = a2 (unused, same reason)
    const float* w3 = (const float*)d_in[13];
    const float* g3 = (const float*)d_in[14];
    const float* b3 = (const float*)d_in[15];
    const float* m3 = (const float*)d_in[16];
    const float* v3 = (const float*)d_in[17];
    const float* a3 = (const float*)d_in[18];
    const float* ao = (const float*)d_in[19];
    float* out = (float*)d_out;

    prep_kernel<<<68, 256>>>(w1, g1, b1, m1, v1,
                             w2, g2, b2, m2, v2,
                             w3, g3, b3, m3, v3);

    dim3 grid(WW / TW, HH / TH, BB);   // 8 x 16 x 8 = 1024 blocks
    k_fused<<<grid, 256>>>(x, out, a3, ao);
}